// round 6
// baseline (speedup 1.0000x reference)
#include <cuda_runtime.h>
#include <cstdint>

#define N_NODES 100000
#define N_EDGES 1600000
#define D 128
#define SCAN_B 1024
#define N_SCAN_BLOCKS ((N_NODES + SCAN_B - 1) / SCAN_B)   // 98

// ---------------- scratch (device globals; no allocation allowed) ----------------
__device__ __align__(256) float g_dis[N_NODES];               // rsqrt(deg)
__device__ __align__(256) int   g_cnt[N_NODES];               // in-degree (edges only)
__device__ __align__(256) int   g_rowstart[N_NODES];          // CSR row offsets
__device__ __align__(256) int   g_cursor[N_NODES];            // fill cursors
__device__ __align__(256) int   g_bsum[N_SCAN_BLOCKS];        // scan block sums
__device__ __align__(256) int   g_srcA[N_EDGES];              // CSR column (src node)
__device__ __align__(256) float g_val[N_EDGES];               // CSR value (norm)
__device__ __align__(256) float g_h[(size_t)N_NODES * D];     // GEMM output
__device__ __align__(256) float g_x1[(size_t)N_NODES * D];    // layer-1 aggregate
__device__ int g_idx64;                                       // edge_index dtype flag

// ---------------- edge-index access (dtype-agnostic + clamped) ----------------
__device__ __forceinline__ int clampN(int v) {
    v = v < 0 ? 0 : v;
    return v >= N_NODES ? N_NODES - 1 : v;
}

__device__ __forceinline__ int eidx(const void* ei, int is64, size_t pos) {
    if (is64) return clampN((int)((const long long*)ei)[pos]);
    return clampN(((const int*)ei)[pos]);
}

// ---------------- probe: detect int64 vs int32 edge_index ----------------
__global__ void k_probe(const int* __restrict__ ei32) {
    if (threadIdx.x == 0 && blockIdx.x == 0) {
        // int64 node ids (< 2^31) have zero high words at every odd int32 slot.
        int odd_or = 0;
#pragma unroll
        for (int i = 1; i < 128; i += 2) odd_or |= ei32[i];
        g_idx64 = (odd_or == 0) ? 1 : 0;
    }
}

// ---------------- prep ----------------
__global__ void k_prep() {
    int i = blockIdx.x * 256 + threadIdx.x;
    if (i < N_NODES) {
        g_dis[i] = 1.0f;   // self-loop weight pre-added
        g_cnt[i] = 0;
        g_cursor[i] = 0;
    }
}

__global__ void k_deg_cnt(const void* __restrict__ ei, const float* __restrict__ w) {
    int e = blockIdx.x * 256 + threadIdx.x;
    if (e < N_EDGES) {
        int is64 = g_idx64;
        int d = eidx(ei, is64, (size_t)N_EDGES + e);
        atomicAdd(&g_dis[d], w[e]);
        atomicAdd(&g_cnt[d], 1);
    }
}

__global__ void k_fin_deg() {
    int i = blockIdx.x * 256 + threadIdx.x;
    if (i < N_NODES) g_dis[i] = rsqrtf(g_dis[i]);  // deg >= 1 (self-loop)
}

// ---------------- exclusive scan of g_cnt -> g_rowstart (two-level) ----------------
__global__ void k_scan1() {
    __shared__ int sm[SCAN_B];
    int tid = threadIdx.x;
    int i = blockIdx.x * SCAN_B + tid;
    int v = (i < N_NODES) ? g_cnt[i] : 0;
    sm[tid] = v;
    __syncthreads();
#pragma unroll
    for (int off = 1; off < SCAN_B; off <<= 1) {
        int t = (tid >= off) ? sm[tid - off] : 0;
        __syncthreads();
        sm[tid] += t;
        __syncthreads();
    }
    if (i < N_NODES) g_rowstart[i] = sm[tid] - v;        // exclusive
    if (tid == SCAN_B - 1) g_bsum[blockIdx.x] = sm[tid]; // block total
}

__global__ void k_scan2() {
    __shared__ int sm[128];
    int tid = threadIdx.x;
    int v = (tid < N_SCAN_BLOCKS) ? g_bsum[tid] : 0;
    sm[tid] = v;
    __syncthreads();
#pragma unroll
    for (int off = 1; off < 128; off <<= 1) {
        int t = (tid >= off) ? sm[tid - off] : 0;
        __syncthreads();
        sm[tid] += t;
        __syncthreads();
    }
    if (tid < N_SCAN_BLOCKS) g_bsum[tid] = sm[tid] - v;  // exclusive
}

__global__ void k_scan3() {
    int i = blockIdx.x * 256 + threadIdx.x;
    if (i < N_NODES) g_rowstart[i] += g_bsum[i >> 10];
}

// ---------------- CSR fill: per edge, place (src, norm) into dst's row ----------------
__global__ void k_fill(const void* __restrict__ ei, const float* __restrict__ w) {
    int e = blockIdx.x * 256 + threadIdx.x;
    if (e < N_EDGES) {
        int is64 = g_idx64;
        int s = eidx(ei, is64, e);
        int d = eidx(ei, is64, (size_t)N_EDGES + e);
        float nm = g_dis[s] * w[e] * g_dis[d];
        int pos = g_rowstart[d] + atomicAdd(&g_cursor[d], 1);
        pos = pos < 0 ? 0 : (pos >= N_EDGES ? N_EDGES - 1 : pos);
        g_srcA[pos] = s;
        g_val[pos] = nm;
    }
}

// ---------------- GEMM: H = act(A) @ W ; AGG = H * dis^2 (self-loop init) ----------
// a_sel: 0 = Aext (features), 1 = g_x1.  agg_sel: 1 = g_x1, 2 = out_ext.
// act = identity if bias==nullptr else prelu(x + bias, alpha) per K-column.
__global__ void __launch_bounds__(256, 2)
k_gemm(const float* __restrict__ Aext, int a_sel,
       const float* __restrict__ W,
       int agg_sel, float* __restrict__ out_ext,
       const float* __restrict__ bias, const float* __restrict__ alpha)
{
    __shared__ __align__(16) float As[32][132];
    __shared__ __align__(16) float Bs[32][132];

    const float* A = (a_sel == 0) ? Aext : g_x1;
    float* AGG = (agg_sel == 1) ? g_x1 : out_ext;
    float* H = g_h;

    const int tid = threadIdx.x;
    const int m0 = blockIdx.x * 128;
    const int ty = tid >> 4;   // 0..15
    const int tx = tid & 15;   // 0..15

    float acc[8][8];
#pragma unroll
    for (int i = 0; i < 8; i++)
#pragma unroll
        for (int j = 0; j < 8; j++) acc[i][j] = 0.0f;

    for (int k0 = 0; k0 < D; k0 += 32) {
        __syncthreads();
#pragma unroll
        for (int it = 0; it < 4; it++) {
            int idx = tid + it * 256;
            int row = idx >> 3;         // 0..127
            int c4  = idx & 7;          // 0..7
            int gm  = m0 + row;
            float4 v = make_float4(0.f, 0.f, 0.f, 0.f);
            if (gm < N_NODES)
                v = *(const float4*)(A + (size_t)gm * D + k0 + c4 * 4);
            if (bias) {
                int kb = k0 + c4 * 4;
                float bb0 = bias[kb + 0], bb1 = bias[kb + 1], bb2 = bias[kb + 2], bb3 = bias[kb + 3];
                float aa0 = alpha[kb + 0], aa1 = alpha[kb + 1], aa2 = alpha[kb + 2], aa3 = alpha[kb + 3];
                v.x += bb0; v.x = v.x >= 0.f ? v.x : aa0 * v.x;
                v.y += bb1; v.y = v.y >= 0.f ? v.y : aa1 * v.y;
                v.z += bb2; v.z = v.z >= 0.f ? v.z : aa2 * v.z;
                v.w += bb3; v.w = v.w >= 0.f ? v.w : aa3 * v.w;
            }
            As[c4 * 4 + 0][row] = v.x;
            As[c4 * 4 + 1][row] = v.y;
            As[c4 * 4 + 2][row] = v.z;
            As[c4 * 4 + 3][row] = v.w;
        }
#pragma unroll
        for (int it = 0; it < 4; it++) {
            int idx = tid + it * 256;
            int row = idx >> 5;         // 0..31
            int c4  = idx & 31;         // 0..31
            float4 v = *(const float4*)(W + (size_t)(k0 + row) * D + c4 * 4);
            *(float4*)&Bs[row][c4 * 4] = v;
        }
        __syncthreads();

#pragma unroll
        for (int kk = 0; kk < 32; kk++) {
            float a[8], b[8];
            *(float4*)&a[0] = *(const float4*)&As[kk][ty * 4];
            *(float4*)&a[4] = *(const float4*)&As[kk][64 + ty * 4];
            *(float4*)&b[0] = *(const float4*)&Bs[kk][tx * 4];
            *(float4*)&b[4] = *(const float4*)&Bs[kk][64 + tx * 4];
#pragma unroll
            for (int i = 0; i < 8; i++)
#pragma unroll
                for (int j = 0; j < 8; j++) acc[i][j] += a[i] * b[j];
        }
    }

#pragma unroll
    for (int ih = 0; ih < 2; ih++) {
#pragma unroll
        for (int i = 0; i < 4; i++) {
            int gm = m0 + ih * 64 + ty * 4 + i;
            if (gm >= N_NODES) continue;
            float sn = g_dis[gm];
            sn = sn * sn;
#pragma unroll
            for (int jh = 0; jh < 2; jh++) {
                int col = jh * 64 + tx * 4;
                float4 v;
                v.x = acc[ih * 4 + i][jh * 4 + 0];
                v.y = acc[ih * 4 + i][jh * 4 + 1];
                v.z = acc[ih * 4 + i][jh * 4 + 2];
                v.w = acc[ih * 4 + i][jh * 4 + 3];
                *(float4*)(H + (size_t)gm * D + col) = v;
                float4 vs = make_float4(v.x * sn, v.y * sn, v.z * sn, v.w * sn);
                *(float4*)(AGG + (size_t)gm * D + col) = vs;
            }
        }
    }
}

// ---------------- gather: AGG[dst] += sum over CSR row of H[src]*norm --------------
// One warp per destination node. No atomics.
__global__ void __launch_bounds__(256)
k_gather(int agg_sel, float* __restrict__ out_ext)
{
    int node = blockIdx.x * 8 + (threadIdx.x >> 5);
    if (node >= N_NODES) return;
    int lane = threadIdx.x & 31;

    float* AGG = (agg_sel == 1) ? g_x1 : out_ext;

    int start = g_rowstart[node];
    int cnt = g_cnt[node];
    float* ap = AGG + (size_t)node * D + lane * 4;
    float4 acc = *(float4*)ap;   // self-loop term already there

    int j = 0;
    for (; j + 1 < cnt; j += 2) {
        int s0 = g_srcA[start + j];
        int s1 = g_srcA[start + j + 1];
        float v0 = g_val[start + j];
        float v1 = g_val[start + j + 1];
        float4 h0 = *(const float4*)(g_h + (size_t)s0 * D + lane * 4);
        float4 h1 = *(const float4*)(g_h + (size_t)s1 * D + lane * 4);
        acc.x += h0.x * v0; acc.y += h0.y * v0; acc.z += h0.z * v0; acc.w += h0.w * v0;
        acc.x += h1.x * v1; acc.y += h1.y * v1; acc.z += h1.z * v1; acc.w += h1.w * v1;
    }
    if (j < cnt) {
        int s0 = g_srcA[start + j];
        float v0 = g_val[start + j];
        float4 h0 = *(const float4*)(g_h + (size_t)s0 * D + lane * 4);
        acc.x += h0.x * v0; acc.y += h0.y * v0; acc.z += h0.z * v0; acc.w += h0.w * v0;
    }
    *(float4*)ap = acc;
}

// ---------------- final bias + PReLU on d_out (in place) ----------------
__global__ void k_bias_prelu(float* __restrict__ x,
                             const float* __restrict__ b, const float* __restrict__ a)
{
    int i = blockIdx.x * 256 + threadIdx.x;  // float4 index
    if (i < N_NODES * (D / 4)) {
        int col = (i & 31) * 4;
        float4 v = ((float4*)x)[i];
        v.x += b[col + 0]; v.x = v.x >= 0.f ? v.x : a[col + 0] * v.x;
        v.y += b[col + 1]; v.y = v.y >= 0.f ? v.y : a[col + 1] * v.y;
        v.z += b[col + 2]; v.z = v.z >= 0.f ? v.z : a[col + 2] * v.z;
        v.w += b[col + 3]; v.w = v.w >= 0.f ? v.w : a[col + 3] * v.w;
        ((float4*)x)[i] = v;
    }
}

// ---------------- launch ----------------
extern "C" void kernel_launch(void* const* d_in, const int* in_sizes, int n_in,
                              void* d_out, int out_size)
{
    const float* features = (const float*)d_in[0];
    const void*  ei       = d_in[1];
    const float* ew       = (const float*)d_in[2];
    const float* W1       = (const float*)d_in[3];
    const float* b1       = (const float*)d_in[4];
    const float* a1       = (const float*)d_in[5];
    const float* W2       = (const float*)d_in[6];
    const float* b2       = (const float*)d_in[7];
    const float* a2       = (const float*)d_in[8];
    float* out = (float*)d_out;

    const int nodeBlocks = (N_NODES + 255) / 256;            // 391
    const int edgeBlocks = (N_EDGES + 255) / 256;            // 6250
    const int gemmBlocks = (N_NODES + 127) / 128;            // 782
    const int gathBlocks = (N_NODES + 7) / 8;                // 12500
    const int elemBlocks = (N_NODES * (D / 4) + 255) / 256;  // 12500

    // dtype probe + normalization prep + CSR build
    k_probe<<<1, 32>>>((const int*)ei);
    k_prep<<<nodeBlocks, 256>>>();
    k_deg_cnt<<<edgeBlocks, 256>>>(ei, ew);
    k_fin_deg<<<nodeBlocks, 256>>>();
    k_scan1<<<N_SCAN_BLOCKS, SCAN_B>>>();
    k_scan2<<<1, 128>>>();
    k_scan3<<<nodeBlocks, 256>>>();
    k_fill<<<edgeBlocks, 256>>>(ei, ew);

    // layer 1: h = X@W1 ; x1 = h*dis^2 ; gather edges into x1
    k_gemm<<<gemmBlocks, 256>>>(features, 0, W1, 1, out, nullptr, nullptr);
    k_gather<<<gathBlocks, 256>>>(1, out);

    // layer 2: A-load applies prelu(x1 + b1, a1); h = act(x1)@W2 ; out = h*dis^2
    k_gemm<<<gemmBlocks, 256>>>(features, 1, W2, 2, out, b1, a1);
    k_gather<<<gathBlocks, 256>>>(2, out);

    // final bias + prelu
    k_bias_prelu<<<elemBlocks, 256>>>(out, b2, a2);
}

// round 8
// speedup vs baseline: 1.5105x; 1.5105x over previous
#include <cuda_runtime.h>
#include <cstdint>

#define N_NODES 100000
#define N_EDGES 1600000
#define D 128
#define SCAN_B 1024
#define N_SCAN_BLOCKS ((N_NODES + SCAN_B - 1) / SCAN_B)   // 98

// ---------------- scratch (device globals; no allocation allowed) ----------------
__device__ __align__(256) float g_dis[N_NODES];               // rsqrt(deg)
__device__ __align__(256) int   g_cnt[N_NODES];               // in-degree (edges only)
__device__ __align__(256) int   g_rowstart[N_NODES];          // CSR row offsets
__device__ __align__(256) int   g_cursor[N_NODES];            // fill cursors
__device__ __align__(256) int   g_bsum[N_SCAN_BLOCKS];        // scan block sums
__device__ __align__(256) int   g_srcA[N_EDGES];              // CSR column (src node)
__device__ __align__(256) float g_val[N_EDGES];               // CSR value (norm)
__device__ __align__(256) float g_h[(size_t)N_NODES * D];     // GEMM output
__device__ __align__(256) float g_x1[(size_t)N_NODES * D];    // layer-1 aggregate
__device__ int g_idx64;                                       // edge_index dtype flag

// ---------------- helpers ----------------
__device__ __forceinline__ int clampN(int v) {
    v = v < 0 ? 0 : v;
    return v >= N_NODES ? N_NODES - 1 : v;
}

__device__ __forceinline__ int eidx(const void* ei, int is64, size_t pos) {
    if (is64) return clampN((int)((const long long*)ei)[pos]);
    return clampN(((const int*)ei)[pos]);
}

__device__ __forceinline__ float tf32r(float x) {
    uint32_t r;
    asm("cvt.rna.tf32.f32 %0, %1;" : "=r"(r) : "f"(x));
    return __uint_as_float(r);
}

__device__ __forceinline__ void mma_tf32(float* c, const uint32_t* a, uint32_t b0, uint32_t b1) {
    asm volatile(
        "mma.sync.aligned.m16n8k8.row.col.f32.tf32.tf32.f32 "
        "{%0,%1,%2,%3}, {%4,%5,%6,%7}, {%8,%9}, {%0,%1,%2,%3};"
        : "+f"(c[0]), "+f"(c[1]), "+f"(c[2]), "+f"(c[3])
        : "r"(a[0]), "r"(a[1]), "r"(a[2]), "r"(a[3]), "r"(b0), "r"(b1));
}

// ---------------- probe: detect int64 vs int32 edge_index ----------------
__global__ void k_probe(const int* __restrict__ ei32) {
    if (threadIdx.x == 0 && blockIdx.x == 0) {
        int odd_or = 0;
#pragma unroll
        for (int i = 1; i < 128; i += 2) odd_or |= ei32[i];
        g_idx64 = (odd_or == 0) ? 1 : 0;
    }
}

// ---------------- prep ----------------
__global__ void k_prep() {
    int i = blockIdx.x * 256 + threadIdx.x;
    if (i < N_NODES) {
        g_dis[i] = 1.0f;   // self-loop weight pre-added
        g_cnt[i] = 0;
        g_cursor[i] = 0;
    }
}

__global__ void k_deg_cnt(const void* __restrict__ ei, const float* __restrict__ w) {
    int e = blockIdx.x * 256 + threadIdx.x;
    if (e < N_EDGES) {
        int is64 = g_idx64;
        int d = eidx(ei, is64, (size_t)N_EDGES + e);
        atomicAdd(&g_dis[d], w[e]);
        atomicAdd(&g_cnt[d], 1);
    }
}

__global__ void k_fin_deg() {
    int i = blockIdx.x * 256 + threadIdx.x;
    if (i < N_NODES) g_dis[i] = rsqrtf(g_dis[i]);
}

// ---------------- exclusive scan of g_cnt -> g_rowstart (two-level) ----------------
__global__ void k_scan1() {
    __shared__ int sm[SCAN_B];
    int tid = threadIdx.x;
    int i = blockIdx.x * SCAN_B + tid;
    int v = (i < N_NODES) ? g_cnt[i] : 0;
    sm[tid] = v;
    __syncthreads();
#pragma unroll
    for (int off = 1; off < SCAN_B; off <<= 1) {
        int t = (tid >= off) ? sm[tid - off] : 0;
        __syncthreads();
        sm[tid] += t;
        __syncthreads();
    }
    if (i < N_NODES) g_rowstart[i] = sm[tid] - v;
    if (tid == SCAN_B - 1) g_bsum[blockIdx.x] = sm[tid];
}

__global__ void k_scan2() {
    __shared__ int sm[128];
    int tid = threadIdx.x;
    int v = (tid < N_SCAN_BLOCKS) ? g_bsum[tid] : 0;
    sm[tid] = v;
    __syncthreads();
#pragma unroll
    for (int off = 1; off < 128; off <<= 1) {
        int t = (tid >= off) ? sm[tid - off] : 0;
        __syncthreads();
        sm[tid] += t;
        __syncthreads();
    }
    if (tid < N_SCAN_BLOCKS) g_bsum[tid] = sm[tid] - v;
}

__global__ void k_scan3() {
    int i = blockIdx.x * 256 + threadIdx.x;
    if (i < N_NODES) g_rowstart[i] += g_bsum[i >> 10];
}

// ---------------- CSR fill ----------------
__global__ void k_fill(const void* __restrict__ ei, const float* __restrict__ w) {
    int e = blockIdx.x * 256 + threadIdx.x;
    if (e < N_EDGES) {
        int is64 = g_idx64;
        int s = eidx(ei, is64, e);
        int d = eidx(ei, is64, (size_t)N_EDGES + e);
        float nm = g_dis[s] * w[e] * g_dis[d];
        int pos = g_rowstart[d] + atomicAdd(&g_cursor[d], 1);
        pos = pos < 0 ? 0 : (pos >= N_EDGES ? N_EDGES - 1 : pos);
        g_srcA[pos] = s;
        g_val[pos] = nm;
    }
}

// ---------------- TF32 tensor-core GEMM: H = act(A) @ W (writes H only) ----------
// a_sel: 0 = Aext (features), 1 = g_x1.
// act = identity if bias==nullptr else prelu(x + bias, alpha) per K-column.
// Block: 128x128 tile, 8 warps (4x2), warp tile 32x64, mma m16n8k8 tf32.
__global__ void __launch_bounds__(256, 2)
k_gemm(const float* __restrict__ Aext, int a_sel, const float* __restrict__ W,
       const float* __restrict__ bias, const float* __restrict__ alpha)
{
    __shared__ float As[128][36];   // [m][k-chunk], stride 36 -> conflict-free frags
    __shared__ float Bs[32][136];   // [k-chunk][n], stride 136 -> conflict-free frags

    const float* A = (a_sel == 0) ? Aext : g_x1;
    float* H = g_h;

    const int tid  = threadIdx.x;
    const int m0   = blockIdx.x * 128;
    const int wid  = tid >> 5, lane = tid & 31;
    const int wm   = wid >> 1, wn = wid & 1;      // warp grid 4x2
    const int gid  = lane >> 2, tig = lane & 3;   // mma fragment coords

    float c[2][8][4];
#pragma unroll
    for (int mt = 0; mt < 2; mt++)
#pragma unroll
        for (int nt = 0; nt < 8; nt++)
#pragma unroll
            for (int q = 0; q < 4; q++) c[mt][nt][q] = 0.0f;

    for (int k0 = 0; k0 < D; k0 += 32) {
        __syncthreads();
        // ---- A chunk: rows m0..m0+127, cols k0..k0+31 (tf32-rounded)
#pragma unroll
        for (int it = 0; it < 4; it++) {
            int idx = tid + it * 256;
            int row = idx >> 3;        // 0..127
            int c4  = idx & 7;         // 0..7
            int gm  = m0 + row;
            float4 v = make_float4(0.f, 0.f, 0.f, 0.f);
            if (gm < N_NODES)
                v = *(const float4*)(A + (size_t)gm * D + k0 + c4 * 4);
            if (bias) {
                int kb = k0 + c4 * 4;
                float bb0 = bias[kb + 0], bb1 = bias[kb + 1], bb2 = bias[kb + 2], bb3 = bias[kb + 3];
                float aa0 = alpha[kb + 0], aa1 = alpha[kb + 1], aa2 = alpha[kb + 2], aa3 = alpha[kb + 3];
                v.x += bb0; v.x = v.x >= 0.f ? v.x : aa0 * v.x;
                v.y += bb1; v.y = v.y >= 0.f ? v.y : aa1 * v.y;
                v.z += bb2; v.z = v.z >= 0.f ? v.z : aa2 * v.z;
                v.w += bb3; v.w = v.w >= 0.f ? v.w : aa3 * v.w;
            }
            As[row][c4 * 4 + 0] = tf32r(v.x);
            As[row][c4 * 4 + 1] = tf32r(v.y);
            As[row][c4 * 4 + 2] = tf32r(v.z);
            As[row][c4 * 4 + 3] = tf32r(v.w);
        }
        // ---- B chunk: W rows k0..k0+31, all 128 cols (tf32-rounded)
#pragma unroll
        for (int it = 0; it < 4; it++) {
            int idx = tid + it * 256;
            int row = idx >> 5;        // 0..31
            int c4  = idx & 31;        // 0..31
            float4 v = *(const float4*)(W + (size_t)(k0 + row) * D + c4 * 4);
            Bs[row][c4 * 4 + 0] = tf32r(v.x);
            Bs[row][c4 * 4 + 1] = tf32r(v.y);
            Bs[row][c4 * 4 + 2] = tf32r(v.z);
            Bs[row][c4 * 4 + 3] = tf32r(v.w);
        }
        __syncthreads();

#pragma unroll
        for (int kk = 0; kk < 32; kk += 8) {
            uint32_t a[2][4];
#pragma unroll
            for (int mt = 0; mt < 2; mt++) {
                int r = wm * 32 + mt * 16 + gid;
                a[mt][0] = __float_as_uint(As[r][kk + tig]);
                a[mt][1] = __float_as_uint(As[r + 8][kk + tig]);
                a[mt][2] = __float_as_uint(As[r][kk + tig + 4]);
                a[mt][3] = __float_as_uint(As[r + 8][kk + tig + 4]);
            }
#pragma unroll
            for (int nt = 0; nt < 8; nt++) {
                int cb = wn * 64 + nt * 8 + gid;
                uint32_t b0 = __float_as_uint(Bs[kk + tig][cb]);
                uint32_t b1 = __float_as_uint(Bs[kk + tig + 4][cb]);
                mma_tf32(c[0][nt], a[0], b0, b1);
                mma_tf32(c[1][nt], a[1], b0, b1);
            }
        }
    }

    // ---- epilogue: write H only (self-loop term handled in gather)
#pragma unroll
    for (int mt = 0; mt < 2; mt++) {
        int r0 = m0 + wm * 32 + mt * 16 + gid;
#pragma unroll
        for (int nt = 0; nt < 8; nt++) {
            int col = wn * 64 + nt * 8 + tig * 2;
            if (r0 < N_NODES)
                *(float2*)(H + (size_t)r0 * D + col) = make_float2(c[mt][nt][0], c[mt][nt][1]);
            if (r0 + 8 < N_NODES)
                *(float2*)(H + (size_t)(r0 + 8) * D + col) = make_float2(c[mt][nt][2], c[mt][nt][3]);
        }
    }
}

// ---------------- gather: AGG[dst] = h[dst]*dis^2 + sum CSR row of h[src]*norm ----
// One warp per destination node; no atomics. Optional fused bias+PReLU epilogue.
__global__ void __launch_bounds__(256)
k_gather(int agg_sel, float* __restrict__ out_ext,
         const float* __restrict__ bias, const float* __restrict__ alpha)
{
    int node = blockIdx.x * 8 + (threadIdx.x >> 5);
    if (node >= N_NODES) return;
    int lane = threadIdx.x & 31;

    float* AGG = (agg_sel == 1) ? g_x1 : out_ext;

    int start = g_rowstart[node];
    int end = start + g_cnt[node];
    float dn = g_dis[node];
    float sn = dn * dn;

    float4 hv = *(const float4*)(g_h + (size_t)node * D + lane * 4);
    float4 acc = make_float4(hv.x * sn, hv.y * sn, hv.z * sn, hv.w * sn);

    int j = start;
    for (; j + 3 < end; j += 4) {
        int s0 = g_srcA[j],     s1 = g_srcA[j + 1];
        int s2 = g_srcA[j + 2], s3 = g_srcA[j + 3];
        float v0 = g_val[j],     v1 = g_val[j + 1];
        float v2 = g_val[j + 2], v3 = g_val[j + 3];
        float4 h0 = *(const float4*)(g_h + (size_t)s0 * D + lane * 4);
        float4 h1 = *(const float4*)(g_h + (size_t)s1 * D + lane * 4);
        float4 h2 = *(const float4*)(g_h + (size_t)s2 * D + lane * 4);
        float4 h3 = *(const float4*)(g_h + (size_t)s3 * D + lane * 4);
        acc.x += h0.x * v0; acc.y += h0.y * v0; acc.z += h0.z * v0; acc.w += h0.w * v0;
        acc.x += h1.x * v1; acc.y += h1.y * v1; acc.z += h1.z * v1; acc.w += h1.w * v1;
        acc.x += h2.x * v2; acc.y += h2.y * v2; acc.z += h2.z * v2; acc.w += h2.w * v2;
        acc.x += h3.x * v3; acc.y += h3.y * v3; acc.z += h3.z * v3; acc.w += h3.w * v3;
    }
    for (; j < end; j++) {
        int s0 = g_srcA[j];
        float v0 = g_val[j];
        float4 h0 = *(const float4*)(g_h + (size_t)s0 * D + lane * 4);
        acc.x += h0.x * v0; acc.y += h0.y * v0; acc.z += h0.z * v0; acc.w += h0.w * v0;
    }

    if (bias) {
        int col = lane * 4;
        acc.x += bias[col + 0]; acc.x = acc.x >= 0.f ? acc.x : alpha[col + 0] * acc.x;
        acc.y += bias[col + 1]; acc.y = acc.y >= 0.f ? acc.y : alpha[col + 1] * acc.y;
        acc.z += bias[col + 2]; acc.z = acc.z >= 0.f ? acc.z : alpha[col + 2] * acc.z;
        acc.w += bias[col + 3]; acc.w = acc.w >= 0.f ? acc.w : alpha[col + 3] * acc.w;
    }
    *(float4*)(AGG + (size_t)node * D + lane * 4) = acc;
}

// ---------------- launch ----------------
extern "C" void kernel_launch(void* const* d_in, const int* in_sizes, int n_in,
                              void* d_out, int out_size)
{
    const float* features = (const float*)d_in[0];
    const void*  ei       = d_in[1];
    const float* ew       = (const float*)d_in[2];
    const float* W1       = (const float*)d_in[3];
    const float* b1       = (const float*)d_in[4];
    const float* a1       = (const float*)d_in[5];
    const float* W2       = (const float*)d_in[6];
    const float* b2       = (const float*)d_in[7];
    const float* a2       = (const float*)d_in[8];
    float* out = (float*)d_out;

    const int nodeBlocks = (N_NODES + 255) / 256;            // 391
    const int edgeBlocks = (N_EDGES + 255) / 256;            // 6250
    const int gemmBlocks = (N_NODES + 127) / 128;            // 782
    const int gathBlocks = (N_NODES + 7) / 8;                // 12500

    // dtype probe + normalization prep + CSR build
    k_probe<<<1, 32>>>((const int*)ei);
    k_prep<<<nodeBlocks, 256>>>();
    k_deg_cnt<<<edgeBlocks, 256>>>(ei, ew);
    k_fin_deg<<<nodeBlocks, 256>>>();
    k_scan1<<<N_SCAN_BLOCKS, SCAN_B>>>();
    k_scan2<<<1, 128>>>();
    k_scan3<<<nodeBlocks, 256>>>();
    k_fill<<<edgeBlocks, 256>>>(ei, ew);

    // layer 1: h = X@W1 ; gather: x1 = h*dis^2 + edge aggregate
    k_gemm<<<gemmBlocks, 256>>>(features, 0, W1, nullptr, nullptr);
    k_gather<<<gathBlocks, 256>>>(1, out, nullptr, nullptr);

    // layer 2: A-load applies prelu(x1 + b1, a1); h = act(x1)@W2 ;
    // gather: out = prelu(h*dis^2 + edge aggregate + b2, a2)
    k_gemm<<<gemmBlocks, 256>>>(features, 1, W2, b1, a1);
    k_gather<<<gathBlocks, 256>>>(2, out, b2, a2);
}

// round 10
// speedup vs baseline: 1.7706x; 1.1722x over previous
#include <cuda_runtime.h>
#include <cuda_fp16.h>
#include <cstdint>

#define N_NODES 100000
#define N_EDGES 1600000
#define D 128
#define SCAN_B 1024
#define N_SCAN_BLOCKS ((N_NODES + SCAN_B - 1) / SCAN_B)   // 98

// ---------------- scratch (device globals; no allocation allowed) ----------------
__device__ __align__(256) float  g_dis[N_NODES];              // rsqrt(deg)
__device__ __align__(256) int    g_cnt[N_NODES];              // in-degree (edges only)
__device__ __align__(256) int    g_rowstart[N_NODES];         // CSR row offsets
__device__ __align__(256) int    g_cursor[N_NODES];           // fill cursors
__device__ __align__(256) int    g_bsum[N_SCAN_BLOCKS];       // scan block sums
__device__ __align__(256) int2   g_edge[N_EDGES];             // CSR (src, norm-bits)
__device__ __align__(256) __half g_h16[(size_t)N_NODES * D];  // GEMM output (fp16)
__device__ __align__(256) float  g_x1[(size_t)N_NODES * D];   // layer-1 activated out
__device__ int g_idx64;                                       // edge_index dtype flag

// ---------------- helpers ----------------
__device__ __forceinline__ int clampN(int v) {
    v = v < 0 ? 0 : v;
    return v >= N_NODES ? N_NODES - 1 : v;
}

__device__ __forceinline__ int eidx(const void* ei, int is64, size_t pos) {
    if (is64) return clampN((int)((const long long*)ei)[pos]);
    return clampN(((const int*)ei)[pos]);
}

__device__ __forceinline__ float tf32r(float x) {
    uint32_t r;
    asm("cvt.rna.tf32.f32 %0, %1;" : "=r"(r) : "f"(x));
    return __uint_as_float(r);
}

__device__ __forceinline__ void mma_tf32(float* c, const uint32_t* a, uint32_t b0, uint32_t b1) {
    asm volatile(
        "mma.sync.aligned.m16n8k8.row.col.f32.tf32.tf32.f32 "
        "{%0,%1,%2,%3}, {%4,%5,%6,%7}, {%8,%9}, {%0,%1,%2,%3};"
        : "+f"(c[0]), "+f"(c[1]), "+f"(c[2]), "+f"(c[3])
        : "r"(a[0]), "r"(a[1]), "r"(a[2]), "r"(a[3]), "r"(b0), "r"(b1));
}

// load 4 halves at h16 + off (element units), return 4 floats
__device__ __forceinline__ float4 ld_h4(const __half* p) {
    uint2 raw = *(const uint2*)p;
    __half2 p0 = *reinterpret_cast<__half2*>(&raw.x);
    __half2 p1 = *reinterpret_cast<__half2*>(&raw.y);
    float2 f0 = __half22float2(p0);
    float2 f1 = __half22float2(p1);
    return make_float4(f0.x, f0.y, f1.x, f1.y);
}

// ---------------- probe: detect int64 vs int32 edge_index ----------------
__global__ void k_probe(const int* __restrict__ ei32) {
    if (threadIdx.x == 0 && blockIdx.x == 0) {
        int odd_or = 0;
#pragma unroll
        for (int i = 1; i < 128; i += 2) odd_or |= ei32[i];
        g_idx64 = (odd_or == 0) ? 1 : 0;
    }
}

// ---------------- prep ----------------
__global__ void k_prep() {
    int i = blockIdx.x * 256 + threadIdx.x;
    if (i < N_NODES) {
        g_dis[i] = 1.0f;   // self-loop weight pre-added
        g_cnt[i] = 0;
        g_cursor[i] = 0;
    }
}

__global__ void k_deg_cnt(const void* __restrict__ ei, const float* __restrict__ w) {
    int e = blockIdx.x * 256 + threadIdx.x;
    if (e < N_EDGES) {
        int is64 = g_idx64;
        int d = eidx(ei, is64, (size_t)N_EDGES + e);
        atomicAdd(&g_dis[d], w[e]);
        atomicAdd(&g_cnt[d], 1);
    }
}

__global__ void k_fin_deg() {
    int i = blockIdx.x * 256 + threadIdx.x;
    if (i < N_NODES) g_dis[i] = rsqrtf(g_dis[i]);
}

// ---------------- exclusive scan of g_cnt -> g_rowstart (two-level) ----------------
__global__ void k_scan1() {
    __shared__ int sm[SCAN_B];
    int tid = threadIdx.x;
    int i = blockIdx.x * SCAN_B + tid;
    int v = (i < N_NODES) ? g_cnt[i] : 0;
    sm[tid] = v;
    __syncthreads();
#pragma unroll
    for (int off = 1; off < SCAN_B; off <<= 1) {
        int t = (tid >= off) ? sm[tid - off] : 0;
        __syncthreads();
        sm[tid] += t;
        __syncthreads();
    }
    if (i < N_NODES) g_rowstart[i] = sm[tid] - v;
    if (tid == SCAN_B - 1) g_bsum[blockIdx.x] = sm[tid];
}

__global__ void k_scan2() {
    __shared__ int sm[128];
    int tid = threadIdx.x;
    int v = (tid < N_SCAN_BLOCKS) ? g_bsum[tid] : 0;
    sm[tid] = v;
    __syncthreads();
#pragma unroll
    for (int off = 1; off < 128; off <<= 1) {
        int t = (tid >= off) ? sm[tid - off] : 0;
        __syncthreads();
        sm[tid] += t;
        __syncthreads();
    }
    if (tid < N_SCAN_BLOCKS) g_bsum[tid] = sm[tid] - v;
}

__global__ void k_scan3() {
    int i = blockIdx.x * 256 + threadIdx.x;
    if (i < N_NODES) g_rowstart[i] += g_bsum[i >> 10];
}

// ---------------- CSR fill: packed (src, norm) records ----------------
__global__ void k_fill(const void* __restrict__ ei, const float* __restrict__ w) {
    int e = blockIdx.x * 256 + threadIdx.x;
    if (e < N_EDGES) {
        int is64 = g_idx64;
        int s = eidx(ei, is64, e);
        int d = eidx(ei, is64, (size_t)N_EDGES + e);
        float nm = g_dis[s] * w[e] * g_dis[d];
        int pos = g_rowstart[d] + atomicAdd(&g_cursor[d], 1);
        pos = pos < 0 ? 0 : (pos >= N_EDGES ? N_EDGES - 1 : pos);
        g_edge[pos] = make_int2(s, __float_as_int(nm));
    }
}

// ---------------- TF32 tensor-core GEMM: H16 = A @ W (fp16 output) ----------
// a_sel: 0 = Aext (features), 1 = g_x1 (already activated).
// Block: 128x128 tile, 8 warps (4x2), warp tile 32x64, mma m16n8k8 tf32.
__global__ void __launch_bounds__(256, 2)
k_gemm(const float* __restrict__ Aext, int a_sel, const float* __restrict__ W)
{
    __shared__ float As[128][36];   // [m][k-chunk], stride 36 -> conflict-free frags
    __shared__ float Bs[32][136];   // [k-chunk][n], stride 136 -> conflict-free frags

    const float* A = (a_sel == 0) ? Aext : g_x1;

    const int tid  = threadIdx.x;
    const int m0   = blockIdx.x * 128;
    const int wid  = tid >> 5, lane = tid & 31;
    const int wm   = wid >> 1, wn = wid & 1;      // warp grid 4x2
    const int gid  = lane >> 2, tig = lane & 3;   // mma fragment coords

    float c[2][8][4];
#pragma unroll
    for (int mt = 0; mt < 2; mt++)
#pragma unroll
        for (int nt = 0; nt < 8; nt++)
#pragma unroll
            for (int q = 0; q < 4; q++) c[mt][nt][q] = 0.0f;

    for (int k0 = 0; k0 < D; k0 += 32) {
        __syncthreads();
        // ---- A chunk: rows m0..m0+127, cols k0..k0+31 (tf32-rounded)
#pragma unroll
        for (int it = 0; it < 4; it++) {
            int idx = tid + it * 256;
            int row = idx >> 3;        // 0..127
            int c4  = idx & 7;         // 0..7
            int gm  = m0 + row;
            float4 v = make_float4(0.f, 0.f, 0.f, 0.f);
            if (gm < N_NODES)
                v = *(const float4*)(A + (size_t)gm * D + k0 + c4 * 4);
            As[row][c4 * 4 + 0] = tf32r(v.x);
            As[row][c4 * 4 + 1] = tf32r(v.y);
            As[row][c4 * 4 + 2] = tf32r(v.z);
            As[row][c4 * 4 + 3] = tf32r(v.w);
        }
        // ---- B chunk: W rows k0..k0+31, all 128 cols (tf32-rounded)
#pragma unroll
        for (int it = 0; it < 4; it++) {
            int idx = tid + it * 256;
            int row = idx >> 5;        // 0..31
            int c4  = idx & 31;        // 0..31
            float4 v = *(const float4*)(W + (size_t)(k0 + row) * D + c4 * 4);
            Bs[row][c4 * 4 + 0] = tf32r(v.x);
            Bs[row][c4 * 4 + 1] = tf32r(v.y);
            Bs[row][c4 * 4 + 2] = tf32r(v.z);
            Bs[row][c4 * 4 + 3] = tf32r(v.w);
        }
        __syncthreads();

#pragma unroll
        for (int kk = 0; kk < 32; kk += 8) {
            uint32_t a[2][4];
#pragma unroll
            for (int mt = 0; mt < 2; mt++) {
                int r = wm * 32 + mt * 16 + gid;
                a[mt][0] = __float_as_uint(As[r][kk + tig]);
                a[mt][1] = __float_as_uint(As[r + 8][kk + tig]);
                a[mt][2] = __float_as_uint(As[r][kk + tig + 4]);
                a[mt][3] = __float_as_uint(As[r + 8][kk + tig + 4]);
            }
#pragma unroll
            for (int nt = 0; nt < 8; nt++) {
                int cb = wn * 64 + nt * 8 + gid;
                uint32_t b0 = __float_as_uint(Bs[kk + tig][cb]);
                uint32_t b1 = __float_as_uint(Bs[kk + tig + 4][cb]);
                mma_tf32(c[0][nt], a[0], b0, b1);
                mma_tf32(c[1][nt], a[1], b0, b1);
            }
        }
    }

    // ---- epilogue: write H as fp16
#pragma unroll
    for (int mt = 0; mt < 2; mt++) {
        int r0 = m0 + wm * 32 + mt * 16 + gid;
#pragma unroll
        for (int nt = 0; nt < 8; nt++) {
            int col = wn * 64 + nt * 8 + tig * 2;
            if (r0 < N_NODES)
                *(__half2*)(g_h16 + (size_t)r0 * D + col) =
                    __floats2half2_rn(c[mt][nt][0], c[mt][nt][1]);
            if (r0 + 8 < N_NODES)
                *(__half2*)(g_h16 + (size_t)(r0 + 8) * D + col) =
                    __floats2half2_rn(c[mt][nt][2], c[mt][nt][3]);
        }
    }
}

// ---------------- gather: AGG[dst] = prelu(h[dst]*dis^2 + sum h[src]*norm + b, a) --
// One warp per destination node; no atomics. fp16 message reads.
__global__ void __launch_bounds__(256)
k_gather(int agg_sel, float* __restrict__ out_ext,
         const float* __restrict__ bias, const float* __restrict__ alpha)
{
    int node = blockIdx.x * 8 + (threadIdx.x >> 5);
    if (node >= N_NODES) return;
    int lane = threadIdx.x & 31;

    float* AGG = (agg_sel == 1) ? g_x1 : out_ext;

    int start = g_rowstart[node];
    int end = start + g_cnt[node];
    float dn = g_dis[node];
    float sn = dn * dn;

    float4 hv = ld_h4(g_h16 + (size_t)node * D + lane * 4);
    float4 acc = make_float4(hv.x * sn, hv.y * sn, hv.z * sn, hv.w * sn);

    int j = start;
    for (; j + 3 < end; j += 4) {
        int2 e0 = g_edge[j],     e1 = g_edge[j + 1];
        int2 e2 = g_edge[j + 2], e3 = g_edge[j + 3];
        float4 h0 = ld_h4(g_h16 + (size_t)e0.x * D + lane * 4);
        float4 h1 = ld_h4(g_h16 + (size_t)e1.x * D + lane * 4);
        float4 h2 = ld_h4(g_h16 + (size_t)e2.x * D + lane * 4);
        float4 h3 = ld_h4(g_h16 + (size_t)e3.x * D + lane * 4);
        float v0 = __int_as_float(e0.y), v1 = __int_as_float(e1.y);
        float v2 = __int_as_float(e2.y), v3 = __int_as_float(e3.y);
        acc.x += h0.x * v0; acc.y += h0.y * v0; acc.z += h0.z * v0; acc.w += h0.w * v0;
        acc.x += h1.x * v1; acc.y += h1.y * v1; acc.z += h1.z * v1; acc.w += h1.w * v1;
        acc.x += h2.x * v2; acc.y += h2.y * v2; acc.z += h2.z * v2; acc.w += h2.w * v2;
        acc.x += h3.x * v3; acc.y += h3.y * v3; acc.z += h3.z * v3; acc.w += h3.w * v3;
    }
    for (; j < end; j++) {
        int2 e0 = g_edge[j];
        float v0 = __int_as_float(e0.y);
        float4 h0 = ld_h4(g_h16 + (size_t)e0.x * D + lane * 4);
        acc.x += h0.x * v0; acc.y += h0.y * v0; acc.z += h0.z * v0; acc.w += h0.w * v0;
    }

    if (bias) {
        int col = lane * 4;
        acc.x += bias[col + 0]; acc.x = acc.x >= 0.f ? acc.x : alpha[col + 0] * acc.x;
        acc.y += bias[col + 1]; acc.y = acc.y >= 0.f ? acc.y : alpha[col + 1] * acc.y;
        acc.z += bias[col + 2]; acc.z = acc.z >= 0.f ? acc.z : alpha[col + 2] * acc.z;
        acc.w += bias[col + 3]; acc.w = acc.w >= 0.f ? acc.w : alpha[col + 3] * acc.w;
    }
    *(float4*)(AGG + (size_t)node * D + lane * 4) = acc;
}

// ---------------- launch ----------------
extern "C" void kernel_launch(void* const* d_in, const int* in_sizes, int n_in,
                              void* d_out, int out_size)
{
    const float* features = (const float*)d_in[0];
    const void*  ei       = d_in[1];
    const float* ew       = (const float*)d_in[2];
    const float* W1       = (const float*)d_in[3];
    const float* b1       = (const float*)d_in[4];
    const float* a1       = (const float*)d_in[5];
    const float* W2       = (const float*)d_in[6];
    const float* b2       = (const float*)d_in[7];
    const float* a2       = (const float*)d_in[8];
    float* out = (float*)d_out;

    const int nodeBlocks = (N_NODES + 255) / 256;            // 391
    const int edgeBlocks = (N_EDGES + 255) / 256;            // 6250
    const int gemmBlocks = (N_NODES + 127) / 128;            // 782
    const int gathBlocks = (N_NODES + 7) / 8;                // 12500

    // dtype probe + normalization prep + CSR build
    k_probe<<<1, 32>>>((const int*)ei);
    k_prep<<<nodeBlocks, 256>>>();
    k_deg_cnt<<<edgeBlocks, 256>>>(ei, ew);
    k_fin_deg<<<nodeBlocks, 256>>>();
    k_scan1<<<N_SCAN_BLOCKS, SCAN_B>>>();
    k_scan2<<<1, 128>>>();
    k_scan3<<<nodeBlocks, 256>>>();
    k_fill<<<edgeBlocks, 256>>>(ei, ew);

    // layer 1: h16 = X@W1 ; gather: x1 = prelu(h*dis^2 + edge agg + b1, a1)
    k_gemm<<<gemmBlocks, 256>>>(features, 0, W1);
    k_gather<<<gathBlocks, 256>>>(1, out, b1, a1);

    // layer 2: h16 = x1@W2 ; gather: out = prelu(h*dis^2 + edge agg + b2, a2)
    k_gemm<<<gemmBlocks, 256>>>(features, 1, W2);
    k_gather<<<gathBlocks, 256>>>(2, out, b2, a2);
}

// round 11
// speedup vs baseline: 1.8137x; 1.0243x over previous
#include <cuda_runtime.h>
#include <cuda_fp16.h>
#include <cstdint>

#define N_NODES 100000
#define N_EDGES 1600000
#define D 128
#define SCAN_B 1024
#define N_SCAN_BLOCKS ((N_NODES + SCAN_B - 1) / SCAN_B)   // 98

// ---------------- scratch (device globals; no allocation allowed) ----------------
__device__ __align__(256) float  g_dis[N_NODES];              // rsqrt(deg)
__device__ __align__(256) int    g_cnt[N_NODES];              // in-degree (edges only)
__device__ __align__(256) int    g_rowstart[N_NODES];         // CSR row offsets
__device__ __align__(256) int    g_cursor[N_NODES];           // fill cursors (pre-offset)
__device__ __align__(256) int    g_bsum[N_SCAN_BLOCKS];       // scan block sums
__device__ __align__(256) int2   g_edge[N_EDGES];             // CSR (src, norm-bits)
__device__ __align__(256) __half g_h16[(size_t)N_NODES * D];  // GEMM output (fp16)
__device__ __align__(256) float  g_x1[(size_t)N_NODES * D];   // layer-1 activated out
__device__ int g_idx64;                                       // edge_index dtype flag

// ---------------- helpers ----------------
__device__ __forceinline__ int clampN(int v) {
    v = v < 0 ? 0 : v;
    return v >= N_NODES ? N_NODES - 1 : v;
}

__device__ __forceinline__ int eidx(const void* ei, int is64, size_t pos) {
    if (is64) return clampN((int)((const long long*)ei)[pos]);
    return clampN(((const int*)ei)[pos]);
}

__device__ __forceinline__ float tf32r(float x) {
    uint32_t r;
    asm("cvt.rna.tf32.f32 %0, %1;" : "=r"(r) : "f"(x));
    return __uint_as_float(r);
}

__device__ __forceinline__ void mma_tf32(float* c, const uint32_t* a, uint32_t b0, uint32_t b1) {
    asm volatile(
        "mma.sync.aligned.m16n8k8.row.col.f32.tf32.tf32.f32 "
        "{%0,%1,%2,%3}, {%4,%5,%6,%7}, {%8,%9}, {%0,%1,%2,%3};"
        : "+f"(c[0]), "+f"(c[1]), "+f"(c[2]), "+f"(c[3])
        : "r"(a[0]), "r"(a[1]), "r"(a[2]), "r"(a[3]), "r"(b0), "r"(b1));
}

__device__ __forceinline__ float4 ld_h4(const __half* p) {
    uint2 raw = *(const uint2*)p;
    __half2 p0 = *reinterpret_cast<__half2*>(&raw.x);
    __half2 p1 = *reinterpret_cast<__half2*>(&raw.y);
    float2 f0 = __half22float2(p0);
    float2 f1 = __half22float2(p1);
    return make_float4(f0.x, f0.y, f1.x, f1.y);
}

// ---------------- prep (+ dtype probe fused) ----------------
__global__ void k_prep(const int* __restrict__ ei32) {
    int i = blockIdx.x * 256 + threadIdx.x;
    if (i < N_NODES) {
        g_dis[i] = 1.0f;   // self-loop weight pre-added
        g_cnt[i] = 0;
    }
    if (i == 0) {
        // int64 node ids (< 2^31) have zero high words at every odd int32 slot.
        int odd_or = 0;
#pragma unroll
        for (int k = 1; k < 128; k += 2) odd_or |= ei32[k];
        g_idx64 = (odd_or == 0) ? 1 : 0;
    }
}

__global__ void k_deg_cnt(const void* __restrict__ ei, const float* __restrict__ w) {
    int e = blockIdx.x * 256 + threadIdx.x;
    if (e < N_EDGES) {
        int is64 = g_idx64;
        int d = eidx(ei, is64, (size_t)N_EDGES + e);
        atomicAdd(&g_dis[d], w[e]);
        atomicAdd(&g_cnt[d], 1);
    }
}

// ---------------- scan1 (+ fin_deg fused) ----------------
__global__ void k_scan1() {
    __shared__ int sm[SCAN_B];
    int tid = threadIdx.x;
    int i = blockIdx.x * SCAN_B + tid;
    int v = (i < N_NODES) ? g_cnt[i] : 0;
    if (i < N_NODES) g_dis[i] = rsqrtf(g_dis[i]);   // fused degree finalize
    sm[tid] = v;
    __syncthreads();
#pragma unroll
    for (int off = 1; off < SCAN_B; off <<= 1) {
        int t = (tid >= off) ? sm[tid - off] : 0;
        __syncthreads();
        sm[tid] += t;
        __syncthreads();
    }
    if (i < N_NODES) g_rowstart[i] = sm[tid] - v;
    if (tid == SCAN_B - 1) g_bsum[blockIdx.x] = sm[tid];
}

__global__ void k_scan2() {
    __shared__ int sm[128];
    int tid = threadIdx.x;
    int v = (tid < N_SCAN_BLOCKS) ? g_bsum[tid] : 0;
    sm[tid] = v;
    __syncthreads();
#pragma unroll
    for (int off = 1; off < 128; off <<= 1) {
        int t = (tid >= off) ? sm[tid - off] : 0;
        __syncthreads();
        sm[tid] += t;
        __syncthreads();
    }
    if (tid < N_SCAN_BLOCKS) g_bsum[tid] = sm[tid] - v;
}

__global__ void k_scan3() {
    int i = blockIdx.x * 256 + threadIdx.x;
    if (i < N_NODES) {
        int rs = g_rowstart[i] + g_bsum[i >> 10];
        g_rowstart[i] = rs;
        g_cursor[i] = rs;      // cursor pre-offset: fill does a single atomicAdd
    }
}

// ---------------- CSR fill: packed (src, norm) records ----------------
__global__ void k_fill(const void* __restrict__ ei, const float* __restrict__ w) {
    int e = blockIdx.x * 256 + threadIdx.x;
    if (e < N_EDGES) {
        int is64 = g_idx64;
        int s = eidx(ei, is64, e);
        int d = eidx(ei, is64, (size_t)N_EDGES + e);
        float nm = g_dis[s] * w[e] * g_dis[d];
        int pos = atomicAdd(&g_cursor[d], 1);
        pos = pos < 0 ? 0 : (pos >= N_EDGES ? N_EDGES - 1 : pos);
        g_edge[pos] = make_int2(s, __float_as_int(nm));
    }
}

// ---------------- TF32 tensor-core GEMM, double-buffered: H16 = A @ W ----------
// a_sel: 0 = Aext (features), 1 = g_x1 (already activated).
// Block 128x128 tile, 8 warps (4x2), warp tile 32x64, k-chunk 16, 2-stage smem.
__global__ void __launch_bounds__(256, 2)
k_gemm(const float* __restrict__ Aext, int a_sel, const float* __restrict__ W)
{
    __shared__ float As[2][128][20];   // [m][k], stride 20 -> conflict-free frags
    __shared__ float Bs[2][16][136];   // [k][n], stride 136 -> conflict-free frags

    const float* A = (a_sel == 0) ? Aext : g_x1;

    const int tid  = threadIdx.x;
    const int m0   = blockIdx.x * 128;
    const int wid  = tid >> 5, lane = tid & 31;
    const int wm   = wid >> 1, wn = wid & 1;      // warp grid 4x2
    const int gid  = lane >> 2, tig = lane & 3;   // mma fragment coords

    // per-chunk load coords (2 float4 each for A and B)
    const int ar0 = tid >> 1, ac0 = (tid & 1) * 4;           // A: idx = tid*? -> see below
    const int br0 = tid >> 5, bc0 = (tid & 31) * 4;

    float c[2][8][4];
#pragma unroll
    for (int mt = 0; mt < 2; mt++)
#pragma unroll
        for (int nt = 0; nt < 8; nt++)
#pragma unroll
            for (int q = 0; q < 4; q++) c[mt][nt][q] = 0.0f;

    float4 ra[2], rb[2];

    // A layout per chunk: 128 rows x 16 cols = 512 float4; thread t handles
    //   idx = t and t+256:  row = idx>>2, c4 = idx&3
    // B layout per chunk: 16 rows x 128 cols = 512 float4; idx: row=idx>>5, c4=idx&31
    auto load_chunk = [&](int ch) {
#pragma unroll
        for (int it = 0; it < 2; it++) {
            int idx = tid + it * 256;
            int row = idx >> 2, c4 = idx & 3;
            int gm = m0 + row;
            float4 v = make_float4(0.f, 0.f, 0.f, 0.f);
            if (gm < N_NODES)
                v = *(const float4*)(A + (size_t)gm * D + ch * 16 + c4 * 4);
            ra[it] = v;
        }
#pragma unroll
        for (int it = 0; it < 2; it++) {
            int idx = tid + it * 256;
            int row = idx >> 5, c4 = idx & 31;
            rb[it] = *(const float4*)(W + (size_t)(ch * 16 + row) * D + c4 * 4);
        }
    };

    auto store_chunk = [&](int buf) {
#pragma unroll
        for (int it = 0; it < 2; it++) {
            int idx = tid + it * 256;
            int row = idx >> 2, c4 = idx & 3;
            As[buf][row][c4 * 4 + 0] = tf32r(ra[it].x);
            As[buf][row][c4 * 4 + 1] = tf32r(ra[it].y);
            As[buf][row][c4 * 4 + 2] = tf32r(ra[it].z);
            As[buf][row][c4 * 4 + 3] = tf32r(ra[it].w);
        }
#pragma unroll
        for (int it = 0; it < 2; it++) {
            int idx = tid + it * 256;
            int row = idx >> 5, c4 = idx & 31;
            Bs[buf][row][c4 * 4 + 0] = tf32r(rb[it].x);
            Bs[buf][row][c4 * 4 + 1] = tf32r(rb[it].y);
            Bs[buf][row][c4 * 4 + 2] = tf32r(rb[it].z);
            Bs[buf][row][c4 * 4 + 3] = tf32r(rb[it].w);
        }
    };

    load_chunk(0);
    store_chunk(0);
    __syncthreads();

    const int NCH = D / 16;  // 8
#pragma unroll
    for (int ch = 0; ch < NCH; ch++) {
        int buf = ch & 1;
        if (ch + 1 < NCH) load_chunk(ch + 1);   // global prefetch overlaps compute

#pragma unroll
        for (int kk = 0; kk < 16; kk += 8) {
            uint32_t a[2][4];
#pragma unroll
            for (int mt = 0; mt < 2; mt++) {
                int r = wm * 32 + mt * 16 + gid;
                a[mt][0] = __float_as_uint(As[buf][r][kk + tig]);
                a[mt][1] = __float_as_uint(As[buf][r + 8][kk + tig]);
                a[mt][2] = __float_as_uint(As[buf][r][kk + tig + 4]);
                a[mt][3] = __float_as_uint(As[buf][r + 8][kk + tig + 4]);
            }
#pragma unroll
            for (int nt = 0; nt < 8; nt++) {
                int cb = wn * 64 + nt * 8 + gid;
                uint32_t b0 = __float_as_uint(Bs[buf][kk + tig][cb]);
                uint32_t b1 = __float_as_uint(Bs[buf][kk + tig + 4][cb]);
                mma_tf32(c[0][nt], a[0], b0, b1);
                mma_tf32(c[1][nt], a[1], b0, b1);
            }
        }

        if (ch + 1 < NCH) {
            store_chunk(buf ^ 1);
            __syncthreads();
        }
    }

    // ---- epilogue: write H as fp16
#pragma unroll
    for (int mt = 0; mt < 2; mt++) {
        int r0 = m0 + wm * 32 + mt * 16 + gid;
#pragma unroll
        for (int nt = 0; nt < 8; nt++) {
            int col = wn * 64 + nt * 8 + tig * 2;
            if (r0 < N_NODES)
                *(__half2*)(g_h16 + (size_t)r0 * D + col) =
                    __floats2half2_rn(c[mt][nt][0], c[mt][nt][1]);
            if (r0 + 8 < N_NODES)
                *(__half2*)(g_h16 + (size_t)(r0 + 8) * D + col) =
                    __floats2half2_rn(c[mt][nt][2], c[mt][nt][3]);
        }
    }
}

// ---------------- gather: AGG[dst] = prelu(h[dst]*dis^2 + sum h[src]*norm + b, a) --
__global__ void __launch_bounds__(256)
k_gather(int agg_sel, float* __restrict__ out_ext,
         const float* __restrict__ bias, const float* __restrict__ alpha)
{
    int node = blockIdx.x * 8 + (threadIdx.x >> 5);
    if (node >= N_NODES) return;
    int lane = threadIdx.x & 31;

    float* AGG = (agg_sel == 1) ? g_x1 : out_ext;

    int start = g_rowstart[node];
    int end = start + g_cnt[node];
    float dn = g_dis[node];
    float sn = dn * dn;

    float4 hv = ld_h4(g_h16 + (size_t)node * D + lane * 4);
    float4 acc = make_float4(hv.x * sn, hv.y * sn, hv.z * sn, hv.w * sn);

    int j = start;
    for (; j + 3 < end; j += 4) {
        int2 e0 = g_edge[j],     e1 = g_edge[j + 1];
        int2 e2 = g_edge[j + 2], e3 = g_edge[j + 3];
        float4 h0 = ld_h4(g_h16 + (size_t)e0.x * D + lane * 4);
        float4 h1 = ld_h4(g_h16 + (size_t)e1.x * D + lane * 4);
        float4 h2 = ld_h4(g_h16 + (size_t)e2.x * D + lane * 4);
        float4 h3 = ld_h4(g_h16 + (size_t)e3.x * D + lane * 4);
        float v0 = __int_as_float(e0.y), v1 = __int_as_float(e1.y);
        float v2 = __int_as_float(e2.y), v3 = __int_as_float(e3.y);
        acc.x += h0.x * v0; acc.y += h0.y * v0; acc.z += h0.z * v0; acc.w += h0.w * v0;
        acc.x += h1.x * v1; acc.y += h1.y * v1; acc.z += h1.z * v1; acc.w += h1.w * v1;
        acc.x += h2.x * v2; acc.y += h2.y * v2; acc.z += h2.z * v2; acc.w += h2.w * v2;
        acc.x += h3.x * v3; acc.y += h3.y * v3; acc.z += h3.z * v3; acc.w += h3.w * v3;
    }
    for (; j < end; j++) {
        int2 e0 = g_edge[j];
        float v0 = __int_as_float(e0.y);
        float4 h0 = ld_h4(g_h16 + (size_t)e0.x * D + lane * 4);
        acc.x += h0.x * v0; acc.y += h0.y * v0; acc.z += h0.z * v0; acc.w += h0.w * v0;
    }

    if (bias) {
        int col = lane * 4;
        acc.x += bias[col + 0]; acc.x = acc.x >= 0.f ? acc.x : alpha[col + 0] * acc.x;
        acc.y += bias[col + 1]; acc.y = acc.y >= 0.f ? acc.y : alpha[col + 1] * acc.y;
        acc.z += bias[col + 2]; acc.z = acc.z >= 0.f ? acc.z : alpha[col + 2] * acc.z;
        acc.w += bias[col + 3]; acc.w = acc.w >= 0.f ? acc.w : alpha[col + 3] * acc.w;
    }
    *(float4*)(AGG + (size_t)node * D + lane * 4) = acc;
}

// ---------------- launch ----------------
extern "C" void kernel_launch(void* const* d_in, const int* in_sizes, int n_in,
                              void* d_out, int out_size)
{
    const float* features = (const float*)d_in[0];
    const void*  ei       = d_in[1];
    const float* ew       = (const float*)d_in[2];
    const float* W1       = (const float*)d_in[3];
    const float* b1       = (const float*)d_in[4];
    const float* a1       = (const float*)d_in[5];
    const float* W2       = (const float*)d_in[6];
    const float* b2       = (const float*)d_in[7];
    const float* a2       = (const float*)d_in[8];
    float* out = (float*)d_out;

    const int nodeBlocks = (N_NODES + 255) / 256;            // 391
    const int edgeBlocks = (N_EDGES + 255) / 256;            // 6250
    const int gemmBlocks = (N_NODES + 127) / 128;            // 782
    const int gathBlocks = (N_NODES + 7) / 8;                // 12500

    // prep (+probe) + degree + CSR build
    k_prep<<<nodeBlocks, 256>>>((const int*)ei);
    k_deg_cnt<<<edgeBlocks, 256>>>(ei, ew);
    k_scan1<<<N_SCAN_BLOCKS, SCAN_B>>>();
    k_scan2<<<1, 128>>>();
    k_scan3<<<nodeBlocks, 256>>>();
    k_fill<<<edgeBlocks, 256>>>(ei, ew);

    // layer 1: h16 = X@W1 ; gather: x1 = prelu(h*dis^2 + edge agg + b1, a1)
    k_gemm<<<gemmBlocks, 256>>>(features, 0, W1);
    k_gather<<<gathBlocks, 256>>>(1, out, b1, a1);

    // layer 2: h16 = x1@W2 ; gather: out = prelu(h*dis^2 + edge agg + b2, a2)
    k_gemm<<<gemmBlocks, 256>>>(features, 1, W2);
    k_gather<<<gathBlocks, 256>>>(2, out, b2, a2);
}

// round 12
// speedup vs baseline: 2.0742x; 1.1436x over previous
#include <cuda_runtime.h>
#include <cuda_fp16.h>
#include <cstdint>

#define N_NODES 100000
#define N_EDGES 1600000
#define D 128
#define SCAN_B 1024
#define N_SCAN_BLOCKS ((N_NODES + SCAN_B - 1) / SCAN_B)   // 98

// ---------------- scratch (device globals; no allocation allowed) ----------------
__device__ __align__(256) unsigned long long g_deg64[N_NODES]; // packed (cnt<<40 | wsum q20)
__device__ __align__(256) float  g_dis[N_NODES];              // rsqrt(deg)
__device__ __align__(256) int    g_cnt[N_NODES];              // in-degree (edges only)
__device__ __align__(256) int    g_rowstart[N_NODES];         // CSR row offsets
__device__ __align__(256) int    g_cursor[N_NODES];           // fill cursors (pre-offset)
__device__ __align__(256) int    g_bsum[N_SCAN_BLOCKS];       // scan block sums
__device__ __align__(256) int2   g_edge[N_EDGES];             // CSR (src, norm-bits)
__device__ __align__(256) __half g_h16[(size_t)N_NODES * D];  // GEMM output (fp16)
__device__ __align__(256) float  g_x1[(size_t)N_NODES * D];   // layer-1 activated out
__device__ int g_idx64;                                       // edge_index dtype flag

// ---------------- helpers ----------------
__device__ __forceinline__ int clampN(int v) {
    v = v < 0 ? 0 : v;
    return v >= N_NODES ? N_NODES - 1 : v;
}

__device__ __forceinline__ int eidx(const void* ei, int is64, size_t pos) {
    if (is64) return clampN((int)((const long long*)ei)[pos]);
    return clampN(((const int*)ei)[pos]);
}

__device__ __forceinline__ uint32_t smem_u32(const void* p) {
    return (uint32_t)__cvta_generic_to_shared(p);
}

__device__ __forceinline__ void ldm_x4(uint32_t* r, uint32_t addr) {
    asm volatile("ldmatrix.sync.aligned.m8n8.x4.shared.b16 {%0,%1,%2,%3}, [%4];"
                 : "=r"(r[0]), "=r"(r[1]), "=r"(r[2]), "=r"(r[3]) : "r"(addr));
}

__device__ __forceinline__ void ldm_x4_t(uint32_t* r, uint32_t addr) {
    asm volatile("ldmatrix.sync.aligned.m8n8.x4.trans.shared.b16 {%0,%1,%2,%3}, [%4];"
                 : "=r"(r[0]), "=r"(r[1]), "=r"(r[2]), "=r"(r[3]) : "r"(addr));
}

__device__ __forceinline__ void mma_f16(float* c, const uint32_t* a, uint32_t b0, uint32_t b1) {
    asm volatile(
        "mma.sync.aligned.m16n8k16.row.col.f32.f16.f16.f32 "
        "{%0,%1,%2,%3}, {%4,%5,%6,%7}, {%8,%9}, {%0,%1,%2,%3};"
        : "+f"(c[0]), "+f"(c[1]), "+f"(c[2]), "+f"(c[3])
        : "r"(a[0]), "r"(a[1]), "r"(a[2]), "r"(a[3]), "r"(b0), "r"(b1));
}

__device__ __forceinline__ float4 ld_h4(const __half* p) {
    uint2 raw = *(const uint2*)p;
    __half2 p0 = *reinterpret_cast<__half2*>(&raw.x);
    __half2 p1 = *reinterpret_cast<__half2*>(&raw.y);
    float2 f0 = __half22float2(p0);
    float2 f1 = __half22float2(p1);
    return make_float4(f0.x, f0.y, f1.x, f1.y);
}

// ---------------- prep (+ dtype probe fused) ----------------
__global__ void k_prep(const int* __restrict__ ei32) {
    int i = blockIdx.x * 256 + threadIdx.x;
    if (i < N_NODES) g_deg64[i] = 0ULL;
    if (i == 0) {
        int odd_or = 0;
#pragma unroll
        for (int k = 1; k < 128; k += 2) odd_or |= ei32[k];
        g_idx64 = (odd_or == 0) ? 1 : 0;
    }
}

// ---------------- degree + count: ONE packed 64-bit atomic per edge ----------------
__global__ void k_deg_cnt(const void* __restrict__ ei, const float* __restrict__ w) {
    int e = blockIdx.x * 256 + threadIdx.x;
    if (e < N_EDGES) {
        int is64 = g_idx64;
        int d = eidx(ei, is64, (size_t)N_EDGES + e);
        unsigned int q = __float2uint_rn(w[e] * 1048576.0f);   // q20 fixed point
        atomicAdd(&g_deg64[d], (1ULL << 40) | (unsigned long long)q);
    }
}

// ---------------- scan1 (+ degree finalize fused) ----------------
__global__ void k_scan1() {
    __shared__ int sm[SCAN_B];
    int tid = threadIdx.x;
    int i = blockIdx.x * SCAN_B + tid;
    int v = 0;
    if (i < N_NODES) {
        unsigned long long p = g_deg64[i];
        v = (int)(p >> 40);
        float wsum = (float)(p & ((1ULL << 40) - 1)) * (1.0f / 1048576.0f);
        g_dis[i] = rsqrtf(wsum + 1.0f);   // +1 self-loop
        g_cnt[i] = v;
    }
    sm[tid] = v;
    __syncthreads();
#pragma unroll
    for (int off = 1; off < SCAN_B; off <<= 1) {
        int t = (tid >= off) ? sm[tid - off] : 0;
        __syncthreads();
        sm[tid] += t;
        __syncthreads();
    }
    if (i < N_NODES) g_rowstart[i] = sm[tid] - v;
    if (tid == SCAN_B - 1) g_bsum[blockIdx.x] = sm[tid];
}

__global__ void k_scan2() {
    __shared__ int sm[128];
    int tid = threadIdx.x;
    int v = (tid < N_SCAN_BLOCKS) ? g_bsum[tid] : 0;
    sm[tid] = v;
    __syncthreads();
#pragma unroll
    for (int off = 1; off < 128; off <<= 1) {
        int t = (tid >= off) ? sm[tid - off] : 0;
        __syncthreads();
        sm[tid] += t;
        __syncthreads();
    }
    if (tid < N_SCAN_BLOCKS) g_bsum[tid] = sm[tid] - v;
}

__global__ void k_scan3() {
    int i = blockIdx.x * 256 + threadIdx.x;
    if (i < N_NODES) {
        int rs = g_rowstart[i] + g_bsum[i >> 10];
        g_rowstart[i] = rs;
        g_cursor[i] = rs;
    }
}

// ---------------- CSR fill: packed (src, norm) records ----------------
__global__ void k_fill(const void* __restrict__ ei, const float* __restrict__ w) {
    int e = blockIdx.x * 256 + threadIdx.x;
    if (e < N_EDGES) {
        int is64 = g_idx64;
        int s = eidx(ei, is64, e);
        int d = eidx(ei, is64, (size_t)N_EDGES + e);
        float nm = g_dis[s] * w[e] * g_dis[d];
        int pos = atomicAdd(&g_cursor[d], 1);
        pos = pos < 0 ? 0 : (pos >= N_EDGES ? N_EDGES - 1 : pos);
        g_edge[pos] = make_int2(s, __float_as_int(nm));
    }
}

// ---------------- FP16 tensor-core GEMM, double-buffered: H16 = A @ W ----------
// a_sel: 0 = Aext (features), 1 = g_x1 (already activated).
// Block 128x128 tile, 8 warps (4x2), warp tile 32x64, k-chunk 16, 2-stage smem.
// mma m16n8k16 f16 inputs / f32 accum (fp16 = 11-bit significand, same as tf32).
__global__ void __launch_bounds__(256, 2)
k_gemm(const float* __restrict__ Aext, int a_sel, const float* __restrict__ W)
{
    __shared__ __half As[2][128][24];   // [m][k], 24-half stride: ldmatrix conflict-free
    __shared__ __half Bs[2][16][136];   // [k][n], 136-half stride: ldmatrix conflict-free

    const float* A = (a_sel == 0) ? Aext : g_x1;

    const int tid  = threadIdx.x;
    const int m0   = blockIdx.x * 128;
    const int wid  = tid >> 5, lane = tid & 31;
    const int wm   = wid >> 1, wn = wid & 1;      // warp grid 4x2
    const int gid  = lane >> 2, tig = lane & 3;   // mma accum coords
    const int li   = lane & 7,  lsel = lane >> 3; // ldmatrix coords

    float c[2][8][4];
#pragma unroll
    for (int mt = 0; mt < 2; mt++)
#pragma unroll
        for (int nt = 0; nt < 8; nt++)
#pragma unroll
            for (int q = 0; q < 4; q++) c[mt][nt][q] = 0.0f;

    float4 ra[2], rb[2];

    // A per chunk: 128 rows x 16 cols fp32 = 512 float4; idx: row=idx>>2, c4=idx&3
    // B per chunk: 16 rows x 128 cols fp32 = 512 float4; idx: row=idx>>5, c4=idx&31
    auto load_chunk = [&](int ch) {
#pragma unroll
        for (int it = 0; it < 2; it++) {
            int idx = tid + it * 256;
            int row = idx >> 2, c4 = idx & 3;
            int gm = m0 + row;
            float4 v = make_float4(0.f, 0.f, 0.f, 0.f);
            if (gm < N_NODES)
                v = *(const float4*)(A + (size_t)gm * D + ch * 16 + c4 * 4);
            ra[it] = v;
        }
#pragma unroll
        for (int it = 0; it < 2; it++) {
            int idx = tid + it * 256;
            int row = idx >> 5, c4 = idx & 31;
            rb[it] = *(const float4*)(W + (size_t)(ch * 16 + row) * D + c4 * 4);
        }
    };

    auto store_chunk = [&](int buf) {
#pragma unroll
        for (int it = 0; it < 2; it++) {
            int idx = tid + it * 256;
            int row = idx >> 2, c4 = idx & 3;
            __half2 h01 = __floats2half2_rn(ra[it].x, ra[it].y);
            __half2 h23 = __floats2half2_rn(ra[it].z, ra[it].w);
            uint2 u = make_uint2(*(uint32_t*)&h01, *(uint32_t*)&h23);
            *(uint2*)&As[buf][row][c4 * 4] = u;
        }
#pragma unroll
        for (int it = 0; it < 2; it++) {
            int idx = tid + it * 256;
            int row = idx >> 5, c4 = idx & 31;
            __half2 h01 = __floats2half2_rn(rb[it].x, rb[it].y);
            __half2 h23 = __floats2half2_rn(rb[it].z, rb[it].w);
            uint2 u = make_uint2(*(uint32_t*)&h01, *(uint32_t*)&h23);
            *(uint2*)&Bs[buf][row][c4 * 4] = u;
        }
    };

    load_chunk(0);
    store_chunk(0);
    __syncthreads();

    const int NCH = D / 16;  // 8
#pragma unroll
    for (int ch = 0; ch < NCH; ch++) {
        int buf = ch & 1;
        if (ch + 1 < NCH) load_chunk(ch + 1);

        // A fragments: 2 m16xk16 tiles via ldmatrix.x4
        uint32_t af[2][4];
#pragma unroll
        for (int mt = 0; mt < 2; mt++) {
            int row = wm * 32 + mt * 16 + (lsel & 1) * 8 + li;
            int col = (lsel >> 1) * 8;
            ldm_x4(af[mt], smem_u32(&As[buf][row][col]));
        }
        // B fragments: 4 k16xn16 tile-pairs via ldmatrix.x4.trans
        uint32_t bf[4][4];
#pragma unroll
        for (int np = 0; np < 4; np++) {
            int row = (lsel & 1) * 8 + li;
            int col = wn * 64 + np * 16 + (lsel >> 1) * 8;
            ldm_x4_t(bf[np], smem_u32(&Bs[buf][row][col]));
        }
#pragma unroll
        for (int mt = 0; mt < 2; mt++)
#pragma unroll
            for (int nt = 0; nt < 8; nt++)
                mma_f16(c[mt][nt], af[mt], bf[nt >> 1][(nt & 1) * 2], bf[nt >> 1][(nt & 1) * 2 + 1]);

        if (ch + 1 < NCH) {
            store_chunk(buf ^ 1);
            __syncthreads();
        }
    }

    // ---- epilogue: write H as fp16 (m16n8 accum layout, same as before)
#pragma unroll
    for (int mt = 0; mt < 2; mt++) {
        int r0 = m0 + wm * 32 + mt * 16 + gid;
#pragma unroll
        for (int nt = 0; nt < 8; nt++) {
            int col = wn * 64 + nt * 8 + tig * 2;
            if (r0 < N_NODES)
                *(__half2*)(g_h16 + (size_t)r0 * D + col) =
                    __floats2half2_rn(c[mt][nt][0], c[mt][nt][1]);
            if (r0 + 8 < N_NODES)
                *(__half2*)(g_h16 + (size_t)(r0 + 8) * D + col) =
                    __floats2half2_rn(c[mt][nt][2], c[mt][nt][3]);
        }
    }
}

// ---------------- gather: AGG[dst] = prelu(h[dst]*dis^2 + sum h[src]*norm + b, a) --
__global__ void __launch_bounds__(256)
k_gather(int agg_sel, float* __restrict__ out_ext,
         const float* __restrict__ bias, const float* __restrict__ alpha)
{
    int node = blockIdx.x * 8 + (threadIdx.x >> 5);
    if (node >= N_NODES) return;
    int lane = threadIdx.x & 31;

    float* AGG = (agg_sel == 1) ? g_x1 : out_ext;

    int start = g_rowstart[node];
    int end = start + g_cnt[node];
    float dn = g_dis[node];
    float sn = dn * dn;

    float4 hv = ld_h4(g_h16 + (size_t)node * D + lane * 4);
    float4 acc = make_float4(hv.x * sn, hv.y * sn, hv.z * sn, hv.w * sn);

    int j = start;
    for (; j + 3 < end; j += 4) {
        int2 e0 = g_edge[j],     e1 = g_edge[j + 1];
        int2 e2 = g_edge[j + 2], e3 = g_edge[j + 3];
        float4 h0 = ld_h4(g_h16 + (size_t)e0.x * D + lane * 4);
        float4 h1 = ld_h4(g_h16 + (size_t)e1.x * D + lane * 4);
        float4 h2 = ld_h4(g_h16 + (size_t)e2.x * D + lane * 4);
        float4 h3 = ld_h4(g_h16 + (size_t)e3.x * D + lane * 4);
        float v0 = __int_as_float(e0.y), v1 = __int_as_float(e1.y);
        float v2 = __int_as_float(e2.y), v3 = __int_as_float(e3.y);
        acc.x += h0.x * v0; acc.y += h0.y * v0; acc.z += h0.z * v0; acc.w += h0.w * v0;
        acc.x += h1.x * v1; acc.y += h1.y * v1; acc.z += h1.z * v1; acc.w += h1.w * v1;
        acc.x += h2.x * v2; acc.y += h2.y * v2; acc.z += h2.z * v2; acc.w += h2.w * v2;
        acc.x += h3.x * v3; acc.y += h3.y * v3; acc.z += h3.z * v3; acc.w += h3.w * v3;
    }
    for (; j < end; j++) {
        int2 e0 = g_edge[j];
        float v0 = __int_as_float(e0.y);
        float4 h0 = ld_h4(g_h16 + (size_t)e0.x * D + lane * 4);
        acc.x += h0.x * v0; acc.y += h0.y * v0; acc.z += h0.z * v0; acc.w += h0.w * v0;
    }

    if (bias) {
        int col = lane * 4;
        acc.x += bias[col + 0]; acc.x = acc.x >= 0.f ? acc.x : alpha[col + 0] * acc.x;
        acc.y += bias[col + 1]; acc.y = acc.y >= 0.f ? acc.y : alpha[col + 1] * acc.y;
        acc.z += bias[col + 2]; acc.z = acc.z >= 0.f ? acc.z : alpha[col + 2] * acc.z;
        acc.w += bias[col + 3]; acc.w = acc.w >= 0.f ? acc.w : alpha[col + 3] * acc.w;
    }
    *(float4*)(AGG + (size_t)node * D + lane * 4) = acc;
}

// ---------------- launch ----------------
extern "C" void kernel_launch(void* const* d_in, const int* in_sizes, int n_in,
                              void* d_out, int out_size)
{
    const float* features = (const float*)d_in[0];
    const void*  ei       = d_in[1];
    const float* ew       = (const float*)d_in[2];
    const float* W1       = (const float*)d_in[3];
    const float* b1       = (const float*)d_in[4];
    const float* a1       = (const float*)d_in[5];
    const float* W2       = (const float*)d_in[6];
    const float* b2       = (const float*)d_in[7];
    const float* a2       = (const float*)d_in[8];
    float* out = (float*)d_out;

    const int nodeBlocks = (N_NODES + 255) / 256;            // 391
    const int edgeBlocks = (N_EDGES + 255) / 256;            // 6250
    const int gemmBlocks = (N_NODES + 127) / 128;            // 782
    const int gathBlocks = (N_NODES + 7) / 8;                // 12500

    // prep (+probe) + degree + CSR build
    k_prep<<<nodeBlocks, 256>>>((const int*)ei);
    k_deg_cnt<<<edgeBlocks, 256>>>(ei, ew);
    k_scan1<<<N_SCAN_BLOCKS, SCAN_B>>>();
    k_scan2<<<1, 128>>>();
    k_scan3<<<nodeBlocks, 256>>>();
    k_fill<<<edgeBlocks, 256>>>(ei, ew);

    // layer 1: h16 = X@W1 ; gather: x1 = prelu(h*dis^2 + edge agg + b1, a1)
    k_gemm<<<gemmBlocks, 256>>>(features, 0, W1);
    k_gather<<<gathBlocks, 256>>>(1, out, b1, a1);

    // layer 2: h16 = x1@W2 ; gather: out = prelu(h*dis^2 + edge agg + b2, a2)
    k_gemm<<<gemmBlocks, 256>>>(features, 1, W2);
    k_gather<<<gathBlocks, 256>>>(2, out, b2, a2);
}

// round 13
// speedup vs baseline: 2.1719x; 1.0471x over previous
#include <cuda_runtime.h>
#include <cuda_fp16.h>
#include <cstdint>

#define N_NODES 100000
#define N_EDGES 1600000
#define D 128
#define SCAN_B 1024
#define N_SCAN_BLOCKS ((N_NODES + SCAN_B - 1) / SCAN_B)   // 98

// ---------------- scratch (device globals; no allocation allowed) ----------------
__device__ __align__(256) unsigned long long g_deg64[N_NODES]; // packed (cnt<<40 | wsum q20)
__device__ __align__(256) float  g_dis[N_NODES];              // rsqrt(deg)
__device__ __align__(256) int    g_cnt[N_NODES];              // in-degree (edges only)
__device__ __align__(256) int    g_rowstart[N_NODES];         // CSR row offsets
__device__ __align__(256) int    g_cursor[N_NODES];           // fill cursors (pre-offset)
__device__ __align__(256) int2   g_edge[N_EDGES];             // CSR (src, norm-bits)
__device__ __align__(256) __half g_h16[(size_t)N_NODES * D];  // GEMM output (fp16)
__device__ __align__(256) float  g_x1[(size_t)N_NODES * D];   // layer-1 activated out
__device__ int g_idx64;                                       // edge_index dtype flag
__device__ int g_total;                                       // scan offset counter

// ---------------- helpers ----------------
__device__ __forceinline__ int clampN(int v) {
    v = v < 0 ? 0 : v;
    return v >= N_NODES ? N_NODES - 1 : v;
}

__device__ __forceinline__ int eidx(const void* ei, int is64, size_t pos) {
    if (is64) return clampN((int)((const long long*)ei)[pos]);
    return clampN(((const int*)ei)[pos]);
}

__device__ __forceinline__ uint32_t smem_u32(const void* p) {
    return (uint32_t)__cvta_generic_to_shared(p);
}

__device__ __forceinline__ void ldm_x4(uint32_t* r, uint32_t addr) {
    asm volatile("ldmatrix.sync.aligned.m8n8.x4.shared.b16 {%0,%1,%2,%3}, [%4];"
                 : "=r"(r[0]), "=r"(r[1]), "=r"(r[2]), "=r"(r[3]) : "r"(addr));
}

__device__ __forceinline__ void ldm_x4_t(uint32_t* r, uint32_t addr) {
    asm volatile("ldmatrix.sync.aligned.m8n8.x4.trans.shared.b16 {%0,%1,%2,%3}, [%4];"
                 : "=r"(r[0]), "=r"(r[1]), "=r"(r[2]), "=r"(r[3]) : "r"(addr));
}

__device__ __forceinline__ void mma_f16(float* c, const uint32_t* a, uint32_t b0, uint32_t b1) {
    asm volatile(
        "mma.sync.aligned.m16n8k16.row.col.f32.f16.f16.f32 "
        "{%0,%1,%2,%3}, {%4,%5,%6,%7}, {%8,%9}, {%0,%1,%2,%3};"
        : "+f"(c[0]), "+f"(c[1]), "+f"(c[2]), "+f"(c[3])
        : "r"(a[0]), "r"(a[1]), "r"(a[2]), "r"(a[3]), "r"(b0), "r"(b1));
}

__device__ __forceinline__ float4 ld_h4(const __half* p) {
    uint2 raw = *(const uint2*)p;
    __half2 p0 = *reinterpret_cast<__half2*>(&raw.x);
    __half2 p1 = *reinterpret_cast<__half2*>(&raw.y);
    float2 f0 = __half22float2(p0);
    float2 f1 = __half22float2(p1);
    return make_float4(f0.x, f0.y, f1.x, f1.y);
}

// ---------------- prep (+ dtype probe + scan counter reset) ----------------
__global__ void k_prep(const int* __restrict__ ei32) {
    int i = blockIdx.x * 256 + threadIdx.x;
    if (i < N_NODES) g_deg64[i] = 0ULL;
    if (i == 0) {
        g_total = 0;
        int odd_or = 0;
#pragma unroll
        for (int k = 1; k < 128; k += 2) odd_or |= ei32[k];
        g_idx64 = (odd_or == 0) ? 1 : 0;
    }
}

// ---------------- degree + count: ONE packed 64-bit atomic per edge ----------------
__global__ void k_deg_cnt(const void* __restrict__ ei, const float* __restrict__ w) {
    int e = blockIdx.x * 256 + threadIdx.x;
    if (e < N_EDGES) {
        int is64 = g_idx64;
        int d = eidx(ei, is64, (size_t)N_EDGES + e);
        unsigned int q = __float2uint_rn(w[e] * 1048576.0f);   // q20 fixed point
        atomicAdd(&g_deg64[d], (1ULL << 40) | (unsigned long long)q);
    }
}

// ---------------- single-kernel scan: local scan + atomic block base --------------
// Row base offsets are assignment-order nondeterministic, but each node gets a
// contiguous range of the right size; gather output is unaffected.
__global__ void k_scan() {
    __shared__ int sm[SCAN_B];
    __shared__ int base_sh;
    int tid = threadIdx.x;
    int i = blockIdx.x * SCAN_B + tid;
    int v = 0;
    if (i < N_NODES) {
        unsigned long long p = g_deg64[i];
        v = (int)(p >> 40);
        float wsum = (float)(p & ((1ULL << 40) - 1)) * (1.0f / 1048576.0f);
        g_dis[i] = rsqrtf(wsum + 1.0f);   // +1 self-loop
        g_cnt[i] = v;
    }
    sm[tid] = v;
    __syncthreads();
#pragma unroll
    for (int off = 1; off < SCAN_B; off <<= 1) {
        int t = (tid >= off) ? sm[tid - off] : 0;
        __syncthreads();
        sm[tid] += t;
        __syncthreads();
    }
    if (tid == SCAN_B - 1) base_sh = atomicAdd(&g_total, sm[tid]);
    __syncthreads();
    if (i < N_NODES) {
        int rs = base_sh + sm[tid] - v;
        g_rowstart[i] = rs;
        g_cursor[i] = rs;
    }
}

// ---------------- CSR fill: packed (src, norm) records ----------------
__global__ void k_fill(const void* __restrict__ ei, const float* __restrict__ w) {
    int e = blockIdx.x * 256 + threadIdx.x;
    if (e < N_EDGES) {
        int is64 = g_idx64;
        int s = eidx(ei, is64, e);
        int d = eidx(ei, is64, (size_t)N_EDGES + e);
        float nm = g_dis[s] * w[e] * g_dis[d];
        int pos = atomicAdd(&g_cursor[d], 1);
        pos = pos < 0 ? 0 : (pos >= N_EDGES ? N_EDGES - 1 : pos);
        g_edge[pos] = make_int2(s, __float_as_int(nm));
    }
}

// ---------------- FP16 tensor-core GEMM, double-buffered: H16 = A @ W ----------
__global__ void __launch_bounds__(256, 2)
k_gemm(const float* __restrict__ Aext, int a_sel, const float* __restrict__ W)
{
    __shared__ __half As[2][128][24];   // [m][k], 24-half stride: ldmatrix conflict-free
    __shared__ __half Bs[2][16][136];   // [k][n], 136-half stride: ldmatrix conflict-free

    const float* A = (a_sel == 0) ? Aext : g_x1;

    const int tid  = threadIdx.x;
    const int m0   = blockIdx.x * 128;
    const int wid  = tid >> 5, lane = tid & 31;
    const int wm   = wid >> 1, wn = wid & 1;      // warp grid 4x2
    const int gid  = lane >> 2, tig = lane & 3;   // mma accum coords
    const int li   = lane & 7,  lsel = lane >> 3; // ldmatrix coords

    float c[2][8][4];
#pragma unroll
    for (int mt = 0; mt < 2; mt++)
#pragma unroll
        for (int nt = 0; nt < 8; nt++)
#pragma unroll
            for (int q = 0; q < 4; q++) c[mt][nt][q] = 0.0f;

    float4 ra[2], rb[2];

    auto load_chunk = [&](int ch) {
#pragma unroll
        for (int it = 0; it < 2; it++) {
            int idx = tid + it * 256;
            int row = idx >> 2, c4 = idx & 3;
            int gm = m0 + row;
            float4 v = make_float4(0.f, 0.f, 0.f, 0.f);
            if (gm < N_NODES)
                v = *(const float4*)(A + (size_t)gm * D + ch * 16 + c4 * 4);
            ra[it] = v;
        }
#pragma unroll
        for (int it = 0; it < 2; it++) {
            int idx = tid + it * 256;
            int row = idx >> 5, c4 = idx & 31;
            rb[it] = *(const float4*)(W + (size_t)(ch * 16 + row) * D + c4 * 4);
        }
    };

    auto store_chunk = [&](int buf) {
#pragma unroll
        for (int it = 0; it < 2; it++) {
            int idx = tid + it * 256;
            int row = idx >> 2, c4 = idx & 3;
            __half2 h01 = __floats2half2_rn(ra[it].x, ra[it].y);
            __half2 h23 = __floats2half2_rn(ra[it].z, ra[it].w);
            uint2 u = make_uint2(*(uint32_t*)&h01, *(uint32_t*)&h23);
            *(uint2*)&As[buf][row][c4 * 4] = u;
        }
#pragma unroll
        for (int it = 0; it < 2; it++) {
            int idx = tid + it * 256;
            int row = idx >> 5, c4 = idx & 31;
            __half2 h01 = __floats2half2_rn(rb[it].x, rb[it].y);
            __half2 h23 = __floats2half2_rn(rb[it].z, rb[it].w);
            uint2 u = make_uint2(*(uint32_t*)&h01, *(uint32_t*)&h23);
            *(uint2*)&Bs[buf][row][c4 * 4] = u;
        }
    };

    load_chunk(0);
    store_chunk(0);
    __syncthreads();

    const int NCH = D / 16;  // 8
#pragma unroll
    for (int ch = 0; ch < NCH; ch++) {
        int buf = ch & 1;
        if (ch + 1 < NCH) load_chunk(ch + 1);

        uint32_t af[2][4];
#pragma unroll
        for (int mt = 0; mt < 2; mt++) {
            int row = wm * 32 + mt * 16 + (lsel & 1) * 8 + li;
            int col = (lsel >> 1) * 8;
            ldm_x4(af[mt], smem_u32(&As[buf][row][col]));
        }
        uint32_t bf[4][4];
#pragma unroll
        for (int np = 0; np < 4; np++) {
            int row = (lsel & 1) * 8 + li;
            int col = wn * 64 + np * 16 + (lsel >> 1) * 8;
            ldm_x4_t(bf[np], smem_u32(&Bs[buf][row][col]));
        }
#pragma unroll
        for (int mt = 0; mt < 2; mt++)
#pragma unroll
            for (int nt = 0; nt < 8; nt++)
                mma_f16(c[mt][nt], af[mt], bf[nt >> 1][(nt & 1) * 2], bf[nt >> 1][(nt & 1) * 2 + 1]);

        if (ch + 1 < NCH) {
            store_chunk(buf ^ 1);
            __syncthreads();
        }
    }

#pragma unroll
    for (int mt = 0; mt < 2; mt++) {
        int r0 = m0 + wm * 32 + mt * 16 + gid;
#pragma unroll
        for (int nt = 0; nt < 8; nt++) {
            int col = wn * 64 + nt * 8 + tig * 2;
            if (r0 < N_NODES)
                *(__half2*)(g_h16 + (size_t)r0 * D + col) =
                    __floats2half2_rn(c[mt][nt][0], c[mt][nt][1]);
            if (r0 + 8 < N_NODES)
                *(__half2*)(g_h16 + (size_t)(r0 + 8) * D + col) =
                    __floats2half2_rn(c[mt][nt][2], c[mt][nt][3]);
        }
    }
}

// ---------------- gather: AGG[dst] = prelu(h[dst]*dis^2 + sum h[src]*norm + b, a) --
__global__ void __launch_bounds__(256)
k_gather(int agg_sel, float* __restrict__ out_ext,
         const float* __restrict__ bias, const float* __restrict__ alpha)
{
    int node = blockIdx.x * 8 + (threadIdx.x >> 5);
    if (node >= N_NODES) return;
    int lane = threadIdx.x & 31;

    float* AGG = (agg_sel == 1) ? g_x1 : out_ext;

    int start = g_rowstart[node];
    int end = start + g_cnt[node];
    float dn = g_dis[node];
    float sn = dn * dn;

    float4 hv = ld_h4(g_h16 + (size_t)node * D + lane * 4);
    float4 acc = make_float4(hv.x * sn, hv.y * sn, hv.z * sn, hv.w * sn);

    int j = start;
    for (; j + 3 < end; j += 4) {
        int2 e0 = g_edge[j],     e1 = g_edge[j + 1];
        int2 e2 = g_edge[j + 2], e3 = g_edge[j + 3];
        float4 h0 = ld_h4(g_h16 + (size_t)e0.x * D + lane * 4);
        float4 h1 = ld_h4(g_h16 + (size_t)e1.x * D + lane * 4);
        float4 h2 = ld_h4(g_h16 + (size_t)e2.x * D + lane * 4);
        float4 h3 = ld_h4(g_h16 + (size_t)e3.x * D + lane * 4);
        float v0 = __int_as_float(e0.y), v1 = __int_as_float(e1.y);
        float v2 = __int_as_float(e2.y), v3 = __int_as_float(e3.y);
        acc.x += h0.x * v0; acc.y += h0.y * v0; acc.z += h0.z * v0; acc.w += h0.w * v0;
        acc.x += h1.x * v1; acc.y += h1.y * v1; acc.z += h1.z * v1; acc.w += h1.w * v1;
        acc.x += h2.x * v2; acc.y += h2.y * v2; acc.z += h2.z * v2; acc.w += h2.w * v2;
        acc.x += h3.x * v3; acc.y += h3.y * v3; acc.z += h3.z * v3; acc.w += h3.w * v3;
    }
    for (; j < end; j++) {
        int2 e0 = g_edge[j];
        float v0 = __int_as_float(e0.y);
        float4 h0 = ld_h4(g_h16 + (size_t)e0.x * D + lane * 4);
        acc.x += h0.x * v0; acc.y += h0.y * v0; acc.z += h0.z * v0; acc.w += h0.w * v0;
    }

    if (bias) {
        int col = lane * 4;
        acc.x += bias[col + 0]; acc.x = acc.x >= 0.f ? acc.x : alpha[col + 0] * acc.x;
        acc.y += bias[col + 1]; acc.y = acc.y >= 0.f ? acc.y : alpha[col + 1] * acc.y;
        acc.z += bias[col + 2]; acc.z = acc.z >= 0.f ? acc.z : alpha[col + 2] * acc.z;
        acc.w += bias[col + 3]; acc.w = acc.w >= 0.f ? acc.w : alpha[col + 3] * acc.w;
    }
    *(float4*)(AGG + (size_t)node * D + lane * 4) = acc;
}

// ---------------- launch: fork GEMM-1 parallel to CSR build ----------------
extern "C" void kernel_launch(void* const* d_in, const int* in_sizes, int n_in,
                              void* d_out, int out_size)
{
    const float* features = (const float*)d_in[0];
    const void*  ei       = d_in[1];
    const float* ew       = (const float*)d_in[2];
    const float* W1       = (const float*)d_in[3];
    const float* b1       = (const float*)d_in[4];
    const float* a1       = (const float*)d_in[5];
    const float* W2       = (const float*)d_in[6];
    const float* b2       = (const float*)d_in[7];
    const float* a2       = (const float*)d_in[8];
    float* out = (float*)d_out;

    const int nodeBlocks = (N_NODES + 255) / 256;            // 391
    const int edgeBlocks = (N_EDGES + 255) / 256;            // 6250
    const int gemmBlocks = (N_NODES + 127) / 128;            // 782
    const int gathBlocks = (N_NODES + 7) / 8;                // 12500

    cudaStream_t s2;
    cudaEvent_t ev_fork, ev_join;
    cudaStreamCreateWithFlags(&s2, cudaStreamNonBlocking);
    cudaEventCreateWithFlags(&ev_fork, cudaEventDisableTiming);
    cudaEventCreateWithFlags(&ev_join, cudaEventDisableTiming);

    // fork: GEMM-1 (independent of CSR build) on s2
    cudaEventRecord(ev_fork, 0);
    cudaStreamWaitEvent(s2, ev_fork, 0);
    k_gemm<<<gemmBlocks, 256, 0, s2>>>(features, 0, W1);

    // main stream: prep + degree + scan + CSR fill
    k_prep<<<nodeBlocks, 256>>>((const int*)ei);
    k_deg_cnt<<<edgeBlocks, 256>>>(ei, ew);
    k_scan<<<N_SCAN_BLOCKS, SCAN_B>>>();
    k_fill<<<edgeBlocks, 256>>>(ei, ew);

    // join: gather-1 needs both h16 (s2) and CSR (main)
    cudaEventRecord(ev_join, s2);
    cudaStreamWaitEvent(0, ev_join, 0);

    k_gather<<<gathBlocks, 256>>>(1, out, b1, a1);
    k_gemm<<<gemmBlocks, 256>>>(features, 1, W2);
    k_gather<<<gathBlocks, 256>>>(2, out, b2, a2);

    cudaEventDestroy(ev_fork);
    cudaEventDestroy(ev_join);
    cudaStreamDestroy(s2);
}